// round 11
// baseline (speedup 1.0000x reference)
#include <cuda_runtime.h>
#include <cuda_fp16.h>
#include <cstdint>

// Conv2d 3x3 s1 p1, NCHW fp32 -> implicit GEMM, mma.sync.m16n8k16.f16 (f32 accum).
// k' = tap*64+ic; activations pre-fp16 into 3 kw-shifted h-padded copies.
// R10: 64px(8x8) x 128oc CTA, warp=32x32 (acc=32 regs), 3 CTAs/SM, BK=32, 4 stages.

#define IN_C   64
#define OUT_C  128
#define HWD    112
#define NB     16
#define HW2    (HWD * HWD)
#define KSZ    576
#define BK     32
#define NCHUNK 18
#define LDA    72                      // A halves per k-row (64 px + 8 pad)
#define LDB    136                     // B halves per k-row (128 oc + 8 pad)
#define A_HB   (BK * LDA * 2)          // 4608 B
#define B_HB   (BK * LDB * 2)          // 8704 B
#define STAGE_BYTES (A_HB + B_HB)      // 13312
#define NSTAGE 4
#define LDC    68
#define SMEM_BYTES (NSTAGE * STAGE_BYTES)   // 53248 (>= 128*68*4 = 34816 for epilogue)

#define XS_PLANE   (114 * 112)
#define XS_COPY    (NB * IN_C * XS_PLANE)
#define XS_TOTAL   (3 * XS_COPY)

__device__ __half g_xs[XS_TOTAL];     // [kw][n][ic][h'=114][w=112], zero borders
__device__ __half g_wh[KSZ * OUT_C];  // [k'][oc], k' = tap*64+ic

// ---------------- prep (fused) ----------------
#define XS_BLOCKS 6384                // 16*64*114*14 / 256
#define WH_BLOCKS 288

__global__ void __launch_bounds__(256)
prep_all(const float* __restrict__ x, const float* __restrict__ w) {
    if (blockIdx.x >= XS_BLOCKS) {
        const int idx = (blockIdx.x - XS_BLOCKS) * 256 + threadIdx.x;  // 73728
        const int kp  = idx >> 7;
        const int oc  = idx & 127;
        const int tap = kp >> 6;
        const int ic  = kp & 63;
        g_wh[idx] = __float2half_rn(w[oc * KSZ + ic * 9 + tap]);
        return;
    }
    const int idx = blockIdx.x * 256 + threadIdx.x;
    const int w8  = idx % 14;
    int r  = idx / 14;
    const int hp  = r % 114;  r /= 114;
    const int ic  = r & 63;   r >>= 6;
    const int n   = r;

    uint4 ov[3];
    const int h_in = hp - 1;
    if ((unsigned)h_in < HWD) {
        const float* xr = x + ((size_t)(n * IN_C + ic) * HWD + h_in) * HWD + w8 * 8;
        float4 a = *reinterpret_cast<const float4*>(xr);
        float4 b = *reinterpret_cast<const float4*>(xr + 4);
        float fm1 = (w8 > 0)  ? __ldg(xr - 1) : 0.0f;
        float f8  = (w8 < 13) ? __ldg(xr + 8) : 0.0f;
        uint32_t hu[10];
        hu[0] = __half_as_ushort(__float2half_rn(fm1));
        hu[1] = __half_as_ushort(__float2half_rn(a.x));
        hu[2] = __half_as_ushort(__float2half_rn(a.y));
        hu[3] = __half_as_ushort(__float2half_rn(a.z));
        hu[4] = __half_as_ushort(__float2half_rn(a.w));
        hu[5] = __half_as_ushort(__float2half_rn(b.x));
        hu[6] = __half_as_ushort(__float2half_rn(b.y));
        hu[7] = __half_as_ushort(__float2half_rn(b.z));
        hu[8] = __half_as_ushort(__float2half_rn(b.w));
        hu[9] = __half_as_ushort(__float2half_rn(f8));
#pragma unroll
        for (int kw = 0; kw < 3; kw++) {
            ov[kw].x = hu[kw + 0] | (hu[kw + 1] << 16);
            ov[kw].y = hu[kw + 2] | (hu[kw + 3] << 16);
            ov[kw].z = hu[kw + 4] | (hu[kw + 5] << 16);
            ov[kw].w = hu[kw + 6] | (hu[kw + 7] << 16);
        }
    } else {
        ov[0] = ov[1] = ov[2] = make_uint4(0, 0, 0, 0);
    }
#pragma unroll
    for (int kw = 0; kw < 3; kw++) {
        __half* dst = g_xs + ((size_t)(kw * NB + n) * IN_C + ic) * XS_PLANE
                           + hp * HWD + w8 * 8;
        *reinterpret_cast<uint4*>(dst) = ov[kw];
    }
}

// ---------------- main kernel ----------------
__device__ __forceinline__ void mma_f16(float c[4], const uint32_t a[4],
                                        uint32_t b0, uint32_t b1) {
    asm volatile(
        "mma.sync.aligned.m16n8k16.row.col.f32.f16.f16.f32 "
        "{%0,%1,%2,%3}, {%4,%5,%6,%7}, {%8,%9}, {%0,%1,%2,%3};"
        : "+f"(c[0]), "+f"(c[1]), "+f"(c[2]), "+f"(c[3])
        : "r"(a[0]), "r"(a[1]), "r"(a[2]), "r"(a[3]), "r"(b0), "r"(b1));
}

#define LDSM_T(r0, r1, r2, r3, addr)                                          \
    asm volatile("ldmatrix.sync.aligned.m8n8.x4.trans.shared.b16 "            \
                 "{%0,%1,%2,%3}, [%4];"                                       \
                 : "=r"(r0), "=r"(r1), "=r"(r2), "=r"(r3) : "r"(addr))

__global__ void __launch_bounds__(256, 3)
conv_main(const float* __restrict__ bias, float* __restrict__ out)
{
    extern __shared__ __align__(16) char smc[];
    uint32_t sbase;
    asm("{ .reg .u64 t; cvta.to.shared.u64 t, %1; cvt.u32.u64 %0, t; }"
        : "=r"(sbase) : "l"(smc));

    const int tid  = threadIdx.x;
    const int wid  = tid >> 5;
    const int lane = tid & 31;

    const int b   = blockIdx.x;          // 3136 = 16 images * 196 tiles (8h x 8w)
    const int n   = b / 196;
    const int rem = b - n * 196;
    const int th  = rem / 14;
    const int tw  = rem - th * 14;
    const int h0  = th * 8;
    const int w0  = tw * 8;

    // ---- A-load: 1x 16B per thread (32 ic x 8 hh x 16B = 4KB/chunk) ----
    const char* const xsb = reinterpret_cast<const char*>(g_xs);
    const int aic = tid >> 3;            // 0..31
    const int ahh = tid & 7;             // 0..7
    const long srcA = ((long)(n * IN_C + aic) * 114 + h0 + ahh) * 224 + w0 * 2;
    const uint32_t dstA = (uint32_t)(aic * LDA + ahh * 8) * 2;

    // ---- B-load: 2x 16B per thread ----
    const char* const whb = reinterpret_cast<const char*>(g_wh);
    long  srcB[2];
    uint32_t dstB[2];
#pragma unroll
    for (int s = 0; s < 2; s++) {
        const int seg = tid + s * 256;
        const int kr  = seg >> 4;        // 0..31
        const int ocq = (seg & 15) * 8;
        srcB[s] = (long)(kr * OUT_C + ocq) * 2;
        dstB[s] = (uint32_t)(kr * LDB + ocq) * 2;
    }

    auto issue = [&](int t, int stage) {
        const uint32_t abase = sbase + stage * STAGE_BYTES;
        const uint32_t bbase = abase + A_HB;
        const int tap = t >> 1;
        const int kh  = (tap >= 3) ? ((tap >= 6) ? 2 : 1) : 0;
        const int kw  = tap - kh * 3;
        const long aoff = (long)kw * (XS_COPY * 2)
                        + (long)((t & 1) * 32) * 25536   // ic0 * 114*224
                        + (long)kh * 224;
        asm volatile("cp.async.cg.shared.global [%0], [%1], 16;"
                     :: "r"(abase + dstA), "l"(xsb + srcA + aoff) : "memory");
        const long boff = (long)t * BK * OUT_C * 2;
#pragma unroll
        for (int s = 0; s < 2; s++)
            asm volatile("cp.async.cg.shared.global [%0], [%1], 16;"
                         :: "r"(bbase + dstB[s]), "l"(whb + srcB[s] + boff) : "memory");
    };

    // ---- microkernel coords: 8 warps, warp = 32px x 32oc ----
    const int wm = wid & 1;              // px subtile (32)
    const int wn = wid >> 1;             // oc subtile (32), 0..3
    const uint32_t aoffL = (uint32_t)(((lane >> 4) * 8 + (lane & 7)) * LDA
                                      + wm * 32 + ((lane >> 3) & 1) * 8);
    const uint32_t boffL = (uint32_t)(((((lane >> 3) & 1) * 8) + (lane & 7)) * LDB
                                      + wn * 32 + (lane >> 4) * 8);

    float acc[2][2][2][4];
#pragma unroll
    for (int i = 0; i < 2; i++)
#pragma unroll
        for (int j = 0; j < 2; j++)
#pragma unroll
            for (int h = 0; h < 2; h++)
#pragma unroll
                for (int c = 0; c < 4; c++) acc[i][j][h][c] = 0.0f;

    auto compute = [&](int stage) {
        const uint32_t abase = sbase + stage * STAGE_BYTES;
        const uint32_t bbase = abase + A_HB;
#pragma unroll
        for (int kk2 = 0; kk2 < 2; kk2++) {          // K = 32 = 2 x k16
            uint32_t a[2][4];
#pragma unroll
            for (int i = 0; i < 2; i++)
                LDSM_T(a[i][0], a[i][1], a[i][2], a[i][3],
                       abase + (aoffL + kk2 * 16 * LDA + i * 16) * 2);
#pragma unroll
            for (int j2 = 0; j2 < 2; j2++) {
                uint32_t b0, b1, b2, b3;
                LDSM_T(b0, b1, b2, b3, bbase + (boffL + kk2 * 16 * LDB + j2 * 16) * 2);
                mma_f16(acc[0][j2][0], a[0], b0, b1);
                mma_f16(acc[1][j2][0], a[1], b0, b1);
                mma_f16(acc[0][j2][1], a[0], b2, b3);
                mma_f16(acc[1][j2][1], a[1], b2, b3);
            }
        }
    };

    // ---- pipeline: 4 stages, 3 in flight ----
    issue(0, 0); asm volatile("cp.async.commit_group;" ::: "memory");
    issue(1, 1); asm volatile("cp.async.commit_group;" ::: "memory");
    issue(2, 2); asm volatile("cp.async.commit_group;" ::: "memory");

    for (int t = 0; t < NCHUNK; t++) {
        asm volatile("cp.async.wait_group 2;" ::: "memory");
        __syncthreads();
        compute(t & 3);
        if (t + 3 < NCHUNK) issue(t + 3, (t + 3) & 3);
        asm volatile("cp.async.commit_group;" ::: "memory");
    }

    // ---- epilogue: stage C in SMEM (stride 68, conflict-free), coalesced out ----
    __syncthreads();
    float* const Cs = reinterpret_cast<float*>(smc);
    const int g  = lane >> 2;
    const int t4 = lane & 3;

#pragma unroll
    for (int i = 0; i < 2; i++)
#pragma unroll
        for (int j2 = 0; j2 < 2; j2++)
#pragma unroll
            for (int nh = 0; nh < 2; nh++) {
                const int oc0 = wn * 32 + j2 * 16 + nh * 8 + 2 * t4;
                const int px0 = wm * 32 + i * 16 + g;
                Cs[oc0 * LDC + px0]           = acc[i][j2][nh][0];
                Cs[(oc0 + 1) * LDC + px0]     = acc[i][j2][nh][1];
                Cs[oc0 * LDC + px0 + 8]       = acc[i][j2][nh][2];
                Cs[(oc0 + 1) * LDC + px0 + 8] = acc[i][j2][nh][3];
            }
    __syncthreads();

    // 128 oc x 64 px = 2048 float4-loads/stores over 8 iters
    float* const ob = out + (size_t)n * OUT_C * HW2 + h0 * HWD + w0;
#pragma unroll
    for (int r2 = 0; r2 < 8; r2++) {
        const int f   = tid + 256 * r2;       // (oc, hh, w2)
        const int w2  = f & 1;
        const int hh  = (f >> 1) & 7;
        const int oc  = f >> 4;
        float4 v = *reinterpret_cast<const float4*>(&Cs[oc * LDC + hh * 8 + w2 * 4]);
        const float bv = __ldg(bias + oc);
        v.x += bv; v.y += bv; v.z += bv; v.w += bv;
        *reinterpret_cast<float4*>(ob + (size_t)oc * HW2 + hh * HWD + w2 * 4) = v;
    }
}

extern "C" void kernel_launch(void* const* d_in, const int* in_sizes, int n_in,
                              void* d_out, int out_size)
{
    const float* x    = (const float*)d_in[0];
    const float* w    = (const float*)d_in[1];
    const float* bias = (const float*)d_in[2];
    float* out        = (float*)d_out;

    prep_all<<<XS_BLOCKS + WH_BLOCKS, 256>>>(x, w);

    cudaFuncSetAttribute(conv_main,
                         cudaFuncAttributeMaxDynamicSharedMemorySize, SMEM_BYTES);
    conv_main<<<NB * 196, 256, SMEM_BYTES>>>(bias, out);
}

// round 13
// speedup vs baseline: 1.2227x; 1.2227x over previous
#include <cuda_runtime.h>
#include <cuda_fp16.h>
#include <cstdint>

// Conv2d 3x3 s1 p1, NCHW fp32 -> implicit GEMM, mma.sync.m16n8k16.f16 (f32 accum).
// k' = tap*64+ic; activations pre-fp16 into 3 kw-shifted h-padded copies.
// R12: R11 + fixed epilogue coverage (128 threads -> 32 writeout iters).
// 128-thread CTA (2/SM), 4 warps of 64x64 (MMA:LDSM ratio 4.0), BK=64, 3 stages.

#define IN_C   64
#define OUT_C  128
#define HWD    112
#define NB     16
#define HW2    (HWD * HWD)
#define KSZ    576
#define BK     64
#define NCHUNK 9
#define LDH    136                     // halves per k-row (A: 128px+pad, B: 128oc+pad)
#define TILE_HB (BK * LDH * 2)         // 17408 B per tile
#define STAGE_BYTES (2 * TILE_HB)      // 34816
#define NSTAGE 3
#define SMEM_BYTES (NSTAGE * STAGE_BYTES)   // 104448 (>= 128*132*4 = 67584 for epilogue)

#define XS_PLANE   (114 * 112)
#define XS_COPY    (NB * IN_C * XS_PLANE)
#define XS_TOTAL   (3 * XS_COPY)

__device__ __half g_xs[XS_TOTAL];     // [kw][n][ic][h'=114][w=112], zero borders
__device__ __half g_wh[KSZ * OUT_C];  // [k'][oc], k' = tap*64+ic

// ---------------- prep (fused) ----------------
#define XS_BLOCKS 6384                // 16*64*114*14 / 256
#define WH_BLOCKS 288

__global__ void __launch_bounds__(256)
prep_all(const float* __restrict__ x, const float* __restrict__ w) {
    if (blockIdx.x >= XS_BLOCKS) {
        const int idx = (blockIdx.x - XS_BLOCKS) * 256 + threadIdx.x;  // 73728
        const int kp  = idx >> 7;
        const int oc  = idx & 127;
        const int tap = kp >> 6;
        const int ic  = kp & 63;
        g_wh[idx] = __float2half_rn(w[oc * KSZ + ic * 9 + tap]);
        return;
    }
    const int idx = blockIdx.x * 256 + threadIdx.x;
    const int w8  = idx % 14;
    int r  = idx / 14;
    const int hp  = r % 114;  r /= 114;
    const int ic  = r & 63;   r >>= 6;
    const int n   = r;

    uint4 ov[3];
    const int h_in = hp - 1;
    if ((unsigned)h_in < HWD) {
        const float* xr = x + ((size_t)(n * IN_C + ic) * HWD + h_in) * HWD + w8 * 8;
        float4 a = *reinterpret_cast<const float4*>(xr);
        float4 b = *reinterpret_cast<const float4*>(xr + 4);
        float fm1 = (w8 > 0)  ? __ldg(xr - 1) : 0.0f;
        float f8  = (w8 < 13) ? __ldg(xr + 8) : 0.0f;
        uint32_t hu[10];
        hu[0] = __half_as_ushort(__float2half_rn(fm1));
        hu[1] = __half_as_ushort(__float2half_rn(a.x));
        hu[2] = __half_as_ushort(__float2half_rn(a.y));
        hu[3] = __half_as_ushort(__float2half_rn(a.z));
        hu[4] = __half_as_ushort(__float2half_rn(a.w));
        hu[5] = __half_as_ushort(__float2half_rn(b.x));
        hu[6] = __half_as_ushort(__float2half_rn(b.y));
        hu[7] = __half_as_ushort(__float2half_rn(b.z));
        hu[8] = __half_as_ushort(__float2half_rn(b.w));
        hu[9] = __half_as_ushort(__float2half_rn(f8));
#pragma unroll
        for (int kw = 0; kw < 3; kw++) {
            ov[kw].x = hu[kw + 0] | (hu[kw + 1] << 16);
            ov[kw].y = hu[kw + 2] | (hu[kw + 3] << 16);
            ov[kw].z = hu[kw + 4] | (hu[kw + 5] << 16);
            ov[kw].w = hu[kw + 6] | (hu[kw + 7] << 16);
        }
    } else {
        ov[0] = ov[1] = ov[2] = make_uint4(0, 0, 0, 0);
    }
#pragma unroll
    for (int kw = 0; kw < 3; kw++) {
        __half* dst = g_xs + ((size_t)(kw * NB + n) * IN_C + ic) * XS_PLANE
                           + hp * HWD + w8 * 8;
        *reinterpret_cast<uint4*>(dst) = ov[kw];
    }
}

// ---------------- main kernel ----------------
__device__ __forceinline__ void mma_f16(float c[4], const uint32_t a[4],
                                        uint32_t b0, uint32_t b1) {
    asm volatile(
        "mma.sync.aligned.m16n8k16.row.col.f32.f16.f16.f32 "
        "{%0,%1,%2,%3}, {%4,%5,%6,%7}, {%8,%9}, {%0,%1,%2,%3};"
        : "+f"(c[0]), "+f"(c[1]), "+f"(c[2]), "+f"(c[3])
        : "r"(a[0]), "r"(a[1]), "r"(a[2]), "r"(a[3]), "r"(b0), "r"(b1));
}

#define LDSM_T(r0, r1, r2, r3, addr)                                          \
    asm volatile("ldmatrix.sync.aligned.m8n8.x4.trans.shared.b16 "            \
                 "{%0,%1,%2,%3}, [%4];"                                       \
                 : "=r"(r0), "=r"(r1), "=r"(r2), "=r"(r3) : "r"(addr))

__global__ void __launch_bounds__(128, 2)
conv_main(const float* __restrict__ bias, float* __restrict__ out)
{
    extern __shared__ __align__(16) char smc[];
    uint32_t sbase;
    asm("{ .reg .u64 t; cvta.to.shared.u64 t, %1; cvt.u32.u64 %0, t; }"
        : "=r"(sbase) : "l"(smc));

    const int tid  = threadIdx.x;
    const int wid  = tid >> 5;
    const int lane = tid & 31;

    const int b   = blockIdx.x;          // 1568 = 16 images * 98 tiles (8h x 16w)
    const int n   = b / 98;
    const int rem = b - n * 98;
    const int th  = rem / 7;
    const int tw  = rem - th * 7;
    const int h0  = th * 8;
    const int w0  = tw * 16;

    // ---- A-load: 8x 16B per thread. Chunk = one tap, k-row = ic (0..63). ----
    const char* const xsb = reinterpret_cast<const char*>(g_xs);
    long  srcA[8];
    uint32_t dstA[8];
#pragma unroll
    for (int s = 0; s < 8; s++) {
        const int seg = tid + s * 128;        // 0..1023
        const int ic  = seg >> 4;             // 0..63
        const int sw  = seg & 15;
        const int hh  = sw >> 1;              // 0..7
        const int hf  = sw & 1;
        srcA[s] = ((long)(n * IN_C + ic) * 114 + h0 + hh) * 224 + w0 * 2 + hf * 16;
        dstA[s] = (uint32_t)(ic * LDH + hh * 16 + hf * 8) * 2;
    }
    // ---- B-load: 8x 16B per thread, contiguous per chunk ----
    const char* const whb = reinterpret_cast<const char*>(g_wh);
    long  srcB[8];
    uint32_t dstB[8];
#pragma unroll
    for (int s = 0; s < 8; s++) {
        const int seg = tid + s * 128;
        const int kr  = seg >> 4;             // 0..63
        const int ocq = (seg & 15) * 8;
        srcB[s] = (long)(kr * OUT_C + ocq) * 2;
        dstB[s] = (uint32_t)(kr * LDH + ocq) * 2;
    }

    auto issue = [&](int t, int stage) {
        const uint32_t abase = sbase + stage * STAGE_BYTES;
        const uint32_t bbase = abase + TILE_HB;
        const int kh  = (t >= 3) ? ((t >= 6) ? 2 : 1) : 0;
        const int kw  = t - kh * 3;
        const long aoff = (long)kw * (XS_COPY * 2) + (long)kh * 224;
#pragma unroll
        for (int s = 0; s < 8; s++)
            asm volatile("cp.async.cg.shared.global [%0], [%1], 16;"
                         :: "r"(abase + dstA[s]), "l"(xsb + srcA[s] + aoff) : "memory");
        const long boff = (long)t * BK * OUT_C * 2;
#pragma unroll
        for (int s = 0; s < 8; s++)
            asm volatile("cp.async.cg.shared.global [%0], [%1], 16;"
                         :: "r"(bbase + dstB[s]), "l"(whb + srcB[s] + boff) : "memory");
    };

    // ---- microkernel coords: 4 warps, warp = 64px x 64oc ----
    const int wm = wid & 1;
    const int wn = wid >> 1;
    const uint32_t aoffL = (uint32_t)(((lane >> 4) * 8 + (lane & 7)) * LDH
                                      + wm * 64 + ((lane >> 3) & 1) * 8);
    const uint32_t boffL = (uint32_t)(((((lane >> 3) & 1) * 8) + (lane & 7)) * LDH
                                      + wn * 64 + (lane >> 4) * 8);

    float acc[4][4][2][4];                    // 128 accumulators
#pragma unroll
    for (int i = 0; i < 4; i++)
#pragma unroll
        for (int j = 0; j < 4; j++)
#pragma unroll
            for (int h = 0; h < 2; h++)
#pragma unroll
                for (int c = 0; c < 4; c++) acc[i][j][h][c] = 0.0f;

    auto compute = [&](int stage) {
        const uint32_t abase = sbase + stage * STAGE_BYTES;
        const uint32_t bbase = abase + TILE_HB;
#pragma unroll
        for (int kk2 = 0; kk2 < 4; kk2++) {          // K = 64 = 4 x k16
            const uint32_t kof = kk2 * 16 * LDH;
            uint32_t a[4][4];
#pragma unroll
            for (int i = 0; i < 4; i++)
                LDSM_T(a[i][0], a[i][1], a[i][2], a[i][3],
                       abase + (aoffL + kof + i * 16) * 2);
#pragma unroll
            for (int j2 = 0; j2 < 4; j2++) {
                uint32_t b0, b1, b2, b3;
                LDSM_T(b0, b1, b2, b3, bbase + (boffL + kof + j2 * 16) * 2);
#pragma unroll
                for (int i = 0; i < 4; i++) {
                    mma_f16(acc[i][j2][0], a[i], b0, b1);
                    mma_f16(acc[i][j2][1], a[i], b2, b3);
                }
            }
        }
    };

    // ---- pipeline: 3 stages, 2 in flight ----
    issue(0, 0); asm volatile("cp.async.commit_group;" ::: "memory");
    issue(1, 1); asm volatile("cp.async.commit_group;" ::: "memory");

    int cst = 0, ist = 2;
    for (int t = 0; t < NCHUNK; t++) {
        asm volatile("cp.async.wait_group 1;" ::: "memory");
        __syncthreads();
        compute(cst);
        if (++cst == NSTAGE) cst = 0;
        if (t + 2 < NCHUNK) {
            issue(t + 2, ist);
            if (++ist == NSTAGE) ist = 0;
        }
        asm volatile("cp.async.commit_group;" ::: "memory");
    }

    // ---- epilogue: stage C in SMEM (stride 132, conflict-free), coalesced out ----
    __syncthreads();
    float* const Cs = reinterpret_cast<float*>(smc);
    const int g  = lane >> 2;
    const int t4 = lane & 3;

#pragma unroll
    for (int i = 0; i < 4; i++)
#pragma unroll
        for (int j2 = 0; j2 < 4; j2++)
#pragma unroll
            for (int nh = 0; nh < 2; nh++) {
                const int oc0 = wn * 64 + j2 * 16 + nh * 8 + 2 * t4;
                const int px0 = wm * 64 + i * 16 + g;
                Cs[oc0 * 132 + px0]           = acc[i][j2][nh][0];
                Cs[(oc0 + 1) * 132 + px0]     = acc[i][j2][nh][1];
                Cs[oc0 * 132 + px0 + 8]       = acc[i][j2][nh][2];
                Cs[(oc0 + 1) * 132 + px0 + 8] = acc[i][j2][nh][3];
            }
    __syncthreads();

    // full C tile: 128 oc x 128 px = 4096 float4 -> 128 threads x 32 iters
    float* const ob = out + (size_t)n * OUT_C * HW2 + h0 * HWD + w0;
#pragma unroll
    for (int r2 = 0; r2 < 32; r2++) {
        const int f   = tid + 128 * r2;       // (oc, hh, w4)
        const int w4  = f & 3;
        const int hh  = (f >> 2) & 7;
        const int oc  = f >> 5;
        float4 v = *reinterpret_cast<const float4*>(&Cs[oc * 132 + hh * 16 + w4 * 4]);
        const float bv = __ldg(bias + oc);
        v.x += bv; v.y += bv; v.z += bv; v.w += bv;
        *reinterpret_cast<float4*>(ob + (size_t)oc * HW2 + hh * HWD + w4 * 4) = v;
    }
}

extern "C" void kernel_launch(void* const* d_in, const int* in_sizes, int n_in,
                              void* d_out, int out_size)
{
    const float* x    = (const float*)d_in[0];
    const float* w    = (const float*)d_in[1];
    const float* bias = (const float*)d_in[2];
    float* out        = (float*)d_out;

    prep_all<<<XS_BLOCKS + WH_BLOCKS, 256>>>(x, w);

    cudaFuncSetAttribute(conv_main,
                         cudaFuncAttributeMaxDynamicSharedMemorySize, SMEM_BYTES);
    conv_main<<<NB * 98, 128, SMEM_BYTES>>>(bias, out);
}

// round 15
// speedup vs baseline: 1.2448x; 1.0181x over previous
#include <cuda_runtime.h>
#include <cuda_fp16.h>
#include <cstdint>

// Conv2d 3x3 s1 p1, NCHW fp32 -> implicit GEMM, mma.sync.m16n8k16.f16 (f32 accum).
// k' = tap*64+ic; activations pre-fp16 into 3 kw-shifted h-padded copies.
// R13: R12 + register-level software pipelining (fragment double buffer:
// LDSM for k-step kk2+1 issued BEFORE the 32 MMAs of kk2, hiding LDS latency).

#define IN_C   64
#define OUT_C  128
#define HWD    112
#define NB     16
#define HW2    (HWD * HWD)
#define KSZ    576
#define BK     64
#define NCHUNK 9
#define LDH    136                     // halves per k-row (A: 128px+pad, B: 128oc+pad)
#define TILE_HB (BK * LDH * 2)         // 17408 B per tile
#define STAGE_BYTES (2 * TILE_HB)      // 34816
#define NSTAGE 3
#define SMEM_BYTES (NSTAGE * STAGE_BYTES)   // 104448 (>= 128*132*4 = 67584 for epilogue)

#define XS_PLANE   (114 * 112)
#define XS_COPY    (NB * IN_C * XS_PLANE)
#define XS_TOTAL   (3 * XS_COPY)

__device__ __half g_xs[XS_TOTAL];     // [kw][n][ic][h'=114][w=112], zero borders
__device__ __half g_wh[KSZ * OUT_C];  // [k'][oc], k' = tap*64+ic

// ---------------- prep (fused) ----------------
#define XS_BLOCKS 6384                // 16*64*114*14 / 256
#define WH_BLOCKS 288

__global__ void __launch_bounds__(256)
prep_all(const float* __restrict__ x, const float* __restrict__ w) {
    if (blockIdx.x >= XS_BLOCKS) {
        const int idx = (blockIdx.x - XS_BLOCKS) * 256 + threadIdx.x;  // 73728
        const int kp  = idx >> 7;
        const int oc  = idx & 127;
        const int tap = kp >> 6;
        const int ic  = kp & 63;
        g_wh[idx] = __float2half_rn(w[oc * KSZ + ic * 9 + tap]);
        return;
    }
    const int idx = blockIdx.x * 256 + threadIdx.x;
    const int w8  = idx % 14;
    int r  = idx / 14;
    const int hp  = r % 114;  r /= 114;
    const int ic  = r & 63;   r >>= 6;
    const int n   = r;

    uint4 ov[3];
    const int h_in = hp - 1;
    if ((unsigned)h_in < HWD) {
        const float* xr = x + ((size_t)(n * IN_C + ic) * HWD + h_in) * HWD + w8 * 8;
        float4 a = *reinterpret_cast<const float4*>(xr);
        float4 b = *reinterpret_cast<const float4*>(xr + 4);
        float fm1 = (w8 > 0)  ? __ldg(xr - 1) : 0.0f;
        float f8  = (w8 < 13) ? __ldg(xr + 8) : 0.0f;
        uint32_t hu[10];
        hu[0] = __half_as_ushort(__float2half_rn(fm1));
        hu[1] = __half_as_ushort(__float2half_rn(a.x));
        hu[2] = __half_as_ushort(__float2half_rn(a.y));
        hu[3] = __half_as_ushort(__float2half_rn(a.z));
        hu[4] = __half_as_ushort(__float2half_rn(a.w));
        hu[5] = __half_as_ushort(__float2half_rn(b.x));
        hu[6] = __half_as_ushort(__float2half_rn(b.y));
        hu[7] = __half_as_ushort(__float2half_rn(b.z));
        hu[8] = __half_as_ushort(__float2half_rn(b.w));
        hu[9] = __half_as_ushort(__float2half_rn(f8));
#pragma unroll
        for (int kw = 0; kw < 3; kw++) {
            ov[kw].x = hu[kw + 0] | (hu[kw + 1] << 16);
            ov[kw].y = hu[kw + 2] | (hu[kw + 3] << 16);
            ov[kw].z = hu[kw + 4] | (hu[kw + 5] << 16);
            ov[kw].w = hu[kw + 6] | (hu[kw + 7] << 16);
        }
    } else {
        ov[0] = ov[1] = ov[2] = make_uint4(0, 0, 0, 0);
    }
#pragma unroll
    for (int kw = 0; kw < 3; kw++) {
        __half* dst = g_xs + ((size_t)(kw * NB + n) * IN_C + ic) * XS_PLANE
                           + hp * HWD + w8 * 8;
        *reinterpret_cast<uint4*>(dst) = ov[kw];
    }
}

// ---------------- main kernel ----------------
__device__ __forceinline__ void mma_f16(float c[4], const uint32_t a[4],
                                        uint32_t b0, uint32_t b1) {
    asm volatile(
        "mma.sync.aligned.m16n8k16.row.col.f32.f16.f16.f32 "
        "{%0,%1,%2,%3}, {%4,%5,%6,%7}, {%8,%9}, {%0,%1,%2,%3};"
        : "+f"(c[0]), "+f"(c[1]), "+f"(c[2]), "+f"(c[3])
        : "r"(a[0]), "r"(a[1]), "r"(a[2]), "r"(a[3]), "r"(b0), "r"(b1));
}

#define LDSM_T(r0, r1, r2, r3, addr)                                          \
    asm volatile("ldmatrix.sync.aligned.m8n8.x4.trans.shared.b16 "            \
                 "{%0,%1,%2,%3}, [%4];"                                       \
                 : "=r"(r0), "=r"(r1), "=r"(r2), "=r"(r3) : "r"(addr))

__global__ void __launch_bounds__(128, 2)
conv_main(const float* __restrict__ bias, float* __restrict__ out)
{
    extern __shared__ __align__(16) char smc[];
    uint32_t sbase;
    asm("{ .reg .u64 t; cvta.to.shared.u64 t, %1; cvt.u32.u64 %0, t; }"
        : "=r"(sbase) : "l"(smc));

    const int tid  = threadIdx.x;
    const int wid  = tid >> 5;
    const int lane = tid & 31;

    const int b   = blockIdx.x;          // 1568 = 16 images * 98 tiles (8h x 16w)
    const int n   = b / 98;
    const int rem = b - n * 98;
    const int th  = rem / 7;
    const int tw  = rem - th * 7;
    const int h0  = th * 8;
    const int w0  = tw * 16;

    // ---- A-load: 8x 16B per thread. Chunk = one tap, k-row = ic (0..63). ----
    const char* const xsb = reinterpret_cast<const char*>(g_xs);
    long  srcA[8];
    uint32_t dstA[8];
#pragma unroll
    for (int s = 0; s < 8; s++) {
        const int seg = tid + s * 128;        // 0..1023
        const int ic  = seg >> 4;             // 0..63
        const int sw  = seg & 15;
        const int hh  = sw >> 1;              // 0..7
        const int hf  = sw & 1;
        srcA[s] = ((long)(n * IN_C + ic) * 114 + h0 + hh) * 224 + w0 * 2 + hf * 16;
        dstA[s] = (uint32_t)(ic * LDH + hh * 16 + hf * 8) * 2;
    }
    // ---- B-load: 8x 16B per thread, contiguous per chunk ----
    const char* const whb = reinterpret_cast<const char*>(g_wh);
    long  srcB[8];
    uint32_t dstB[8];
#pragma unroll
    for (int s = 0; s < 8; s++) {
        const int seg = tid + s * 128;
        const int kr  = seg >> 4;             // 0..63
        const int ocq = (seg & 15) * 8;
        srcB[s] = (long)(kr * OUT_C + ocq) * 2;
        dstB[s] = (uint32_t)(kr * LDH + ocq) * 2;
    }

    auto issue = [&](int t, int stage) {
        const uint32_t abase = sbase + stage * STAGE_BYTES;
        const uint32_t bbase = abase + TILE_HB;
        const int kh  = (t >= 3) ? ((t >= 6) ? 2 : 1) : 0;
        const int kw  = t - kh * 3;
        const long aoff = (long)kw * (XS_COPY * 2) + (long)kh * 224;
#pragma unroll
        for (int s = 0; s < 8; s++)
            asm volatile("cp.async.cg.shared.global [%0], [%1], 16;"
                         :: "r"(abase + dstA[s]), "l"(xsb + srcA[s] + aoff) : "memory");
        const long boff = (long)t * BK * OUT_C * 2;
#pragma unroll
        for (int s = 0; s < 8; s++)
            asm volatile("cp.async.cg.shared.global [%0], [%1], 16;"
                         :: "r"(bbase + dstB[s]), "l"(whb + srcB[s] + boff) : "memory");
    };

    // ---- microkernel coords: 4 warps, warp = 64px x 64oc ----
    const int wm = wid & 1;
    const int wn = wid >> 1;
    const uint32_t aoffL = (uint32_t)(((lane >> 4) * 8 + (lane & 7)) * LDH
                                      + wm * 64 + ((lane >> 3) & 1) * 8);
    const uint32_t boffL = (uint32_t)(((((lane >> 3) & 1) * 8) + (lane & 7)) * LDH
                                      + wn * 64 + (lane >> 4) * 8);

    float acc[4][4][2][4];                    // 128 accumulators
#pragma unroll
    for (int i = 0; i < 4; i++)
#pragma unroll
        for (int j = 0; j < 4; j++)
#pragma unroll
            for (int h = 0; h < 2; h++)
#pragma unroll
                for (int c = 0; c < 4; c++) acc[i][j][h][c] = 0.0f;

    // fragment double buffers
    uint32_t af[2][4][4];
    uint32_t bf[2][4][4];

    auto compute = [&](int stage) {
        const uint32_t abase = sbase + stage * STAGE_BYTES;
        const uint32_t bbase = abase + TILE_HB;
        // prologue: fragments for kk2 = 0
#pragma unroll
        for (int i = 0; i < 4; i++)
            LDSM_T(af[0][i][0], af[0][i][1], af[0][i][2], af[0][i][3],
                   abase + (aoffL + i * 16) * 2);
#pragma unroll
        for (int j = 0; j < 4; j++)
            LDSM_T(bf[0][j][0], bf[0][j][1], bf[0][j][2], bf[0][j][3],
                   bbase + (boffL + j * 16) * 2);
#pragma unroll
        for (int kk2 = 0; kk2 < 4; kk2++) {          // K = 64 = 4 x k16
            const int cur = kk2 & 1;
            const int nxt = cur ^ 1;
            if (kk2 < 3) {                           // prefetch next k-step's fragments
                const uint32_t kof = (kk2 + 1) * 16 * LDH;
#pragma unroll
                for (int i = 0; i < 4; i++)
                    LDSM_T(af[nxt][i][0], af[nxt][i][1], af[nxt][i][2], af[nxt][i][3],
                           abase + (aoffL + kof + i * 16) * 2);
#pragma unroll
                for (int j = 0; j < 4; j++)
                    LDSM_T(bf[nxt][j][0], bf[nxt][j][1], bf[nxt][j][2], bf[nxt][j][3],
                           bbase + (boffL + kof + j * 16) * 2);
            }
            // 32 MMAs on current fragments (independent of the LDSMs just issued)
#pragma unroll
            for (int j2 = 0; j2 < 4; j2++)
#pragma unroll
                for (int i = 0; i < 4; i++) {
                    mma_f16(acc[i][j2][0], af[cur][i], bf[cur][j2][0], bf[cur][j2][1]);
                    mma_f16(acc[i][j2][1], af[cur][i], bf[cur][j2][2], bf[cur][j2][3]);
                }
        }
    };

    // ---- pipeline: 3 stages, 2 in flight ----
    issue(0, 0); asm volatile("cp.async.commit_group;" ::: "memory");
    issue(1, 1); asm volatile("cp.async.commit_group;" ::: "memory");

    int cst = 0, ist = 2;
    for (int t = 0; t < NCHUNK; t++) {
        asm volatile("cp.async.wait_group 1;" ::: "memory");
        __syncthreads();
        compute(cst);
        if (++cst == NSTAGE) cst = 0;
        if (t + 2 < NCHUNK) {
            issue(t + 2, ist);
            if (++ist == NSTAGE) ist = 0;
        }
        asm volatile("cp.async.commit_group;" ::: "memory");
    }

    // ---- epilogue: stage C in SMEM (stride 132, conflict-free), coalesced out ----
    __syncthreads();
    float* const Cs = reinterpret_cast<float*>(smc);
    const int g  = lane >> 2;
    const int t4 = lane & 3;

#pragma unroll
    for (int i = 0; i < 4; i++)
#pragma unroll
        for (int j2 = 0; j2 < 4; j2++)
#pragma unroll
            for (int nh = 0; nh < 2; nh++) {
                const int oc0 = wn * 64 + j2 * 16 + nh * 8 + 2 * t4;
                const int px0 = wm * 64 + i * 16 + g;
                Cs[oc0 * 132 + px0]           = acc[i][j2][nh][0];
                Cs[(oc0 + 1) * 132 + px0]     = acc[i][j2][nh][1];
                Cs[oc0 * 132 + px0 + 8]       = acc[i][j2][nh][2];
                Cs[(oc0 + 1) * 132 + px0 + 8] = acc[i][j2][nh][3];
            }
    __syncthreads();

    // full C tile: 128 oc x 128 px = 4096 float4 -> 128 threads x 32 iters
    float* const ob = out + (size_t)n * OUT_C * HW2 + h0 * HWD + w0;
#pragma unroll
    for (int r2 = 0; r2 < 32; r2++) {
        const int f   = tid + 128 * r2;       // (oc, hh, w4)
        const int w4  = f & 3;
        const int hh  = (f >> 2) & 7;
        const int oc  = f >> 5;
        float4 v = *reinterpret_cast<const float4*>(&Cs[oc * 132 + hh * 16 + w4 * 4]);
        const float bv = __ldg(bias + oc);
        v.x += bv; v.y += bv; v.z += bv; v.w += bv;
        *reinterpret_cast<float4*>(ob + (size_t)oc * HW2 + hh * HWD + w4 * 4) = v;
    }
}

extern "C" void kernel_launch(void* const* d_in, const int* in_sizes, int n_in,
                              void* d_out, int out_size)
{
    const float* x    = (const float*)d_in[0];
    const float* w    = (const float*)d_in[1];
    const float* bias = (const float*)d_in[2];
    float* out        = (float*)d_out;

    prep_all<<<XS_BLOCKS + WH_BLOCKS, 256>>>(x, w);

    cudaFuncSetAttribute(conv_main,
                         cudaFuncAttributeMaxDynamicSharedMemorySize, SMEM_BYTES);
    conv_main<<<NB * 98, 128, SMEM_BYTES>>>(bias, out);
}